// round 7
// baseline (speedup 1.0000x reference)
#include <cuda_runtime.h>
#include <cuda_bf16.h>
#include <cstdint>

#define NNODES 50000
#define NEDGES 640000
#define MDIM 128
#define DDIM 128
#define HDIM 64

// ---------------- device scratch (static, no runtime alloc) ----------------
__device__ float g_P[(size_t)NNODES * HDIM];     // per-node projected features + b1
__device__ float g_sumw[NNODES];                 // sum of weights per node
__device__ __nv_bfloat16 g_W1m[HDIM * MDIM];     // W1[:, :128]  (message half), bf16
__device__ __nv_bfloat16 g_W1t[HDIM * DDIM];     // W1[:, 128:]  (node half),    bf16

#define LDA 136              // bf16 elements per row (8-elem pad -> conflict-free ldmatrix)
#define LDAB (LDA * 2)       // 272 bytes

// ------- pnode smem layout (C roundtrips through smem) -------
#define SM_VEC 0
#define SM_WT 256
#define SM_TG 768
#define SM_A 1280
#define SM_B (1280 + 34816)
#define SMEM_BYTES (SM_B + 17408)

// ------- edge kernel smem layout (double-buffered A) -------
#define E_VEC 0                  // 64 floats: W2
#define E_TG0 256                // 64 ints: targets buf 0
#define E_TG1 512                // 64 ints: targets buf 1
#define E_A0 1024                // A bf16 [64][136] buf 0
#define E_A1 (1024 + 17408)      // A bf16 [64][136] buf 1
#define E_B (1024 + 2 * 17408)   // B bf16 [64][136]
#define E_SMEM (E_B + 17408)     // 53248 B -> 3 CTAs/SM
#define EM 64                    // edges per tile
#define NTILES (NEDGES / EM)     // 10000
#define EGRID 456                // persistent CTAs (~3/SM)

// ---------------- helpers ----------------
__device__ __forceinline__ uint32_t smem_u32(const void* p) {
    uint32_t a;
    asm("{ .reg .u64 t; cvta.to.shared.u64 t, %1; cvt.u32.u64 %0, t; }" : "=r"(a) : "l"(p));
    return a;
}

__device__ __forceinline__ void ldm4(uint32_t& r0, uint32_t& r1, uint32_t& r2, uint32_t& r3,
                                     uint32_t addr) {
    asm volatile("ldmatrix.sync.aligned.m8n8.x4.shared.b16 {%0,%1,%2,%3}, [%4];"
                 : "=r"(r0), "=r"(r1), "=r"(r2), "=r"(r3) : "r"(addr));
}

__device__ __forceinline__ void mma16816(float* c, uint32_t a0, uint32_t a1, uint32_t a2,
                                         uint32_t a3, uint32_t b0, uint32_t b1) {
    asm volatile(
        "mma.sync.aligned.m16n8k16.row.col.f32.bf16.bf16.f32 "
        "{%0,%1,%2,%3}, {%4,%5,%6,%7}, {%8,%9}, {%0,%1,%2,%3};"
        : "+f"(c[0]), "+f"(c[1]), "+f"(c[2]), "+f"(c[3])
        : "r"(a0), "r"(a1), "r"(a2), "r"(a3), "r"(b0), "r"(b1));
}

__device__ __forceinline__ void red_add_v4(float* addr, float4 v) {
    asm volatile("red.global.add.v4.f32 [%0], {%1,%2,%3,%4};"
                 :: "l"(addr), "f"(v.x), "f"(v.y), "f"(v.z), "f"(v.w) : "memory");
}

__device__ __forceinline__ void bar_arrive(int id, int cnt) {
    asm volatile("bar.arrive %0, %1;" :: "r"(id), "r"(cnt) : "memory");
}
__device__ __forceinline__ void bar_wait(int id, int cnt) {
    asm volatile("bar.sync %0, %1;" :: "r"(id), "r"(cnt) : "memory");
}

// tanh-form gelu via MUFU (max dev from exact erf-gelu ~3e-4)
__device__ __forceinline__ float gelu_fast(float x) {
    float t = 1.5957692f * fmaf(0.044715f * x, x * x, x);
    return __fdividef(x, 1.0f + __expf(-t));
}

// ---------------- 128x64 GEMM (pnode only): C -> smem at SM_A ----------------
__device__ __forceinline__ void gemm_128x64(char* smem, uint32_t sb, int wid, int lid) {
    float c[2][8][4];
#pragma unroll
    for (int t = 0; t < 2; t++)
#pragma unroll
        for (int n = 0; n < 8; n++)
#pragma unroll
            for (int j = 0; j < 4; j++) c[t][n][j] = 0.f;

    const int lrow = lid & 15;
    const int lcol = (lid >> 4) * 8;

#pragma unroll
    for (int k = 0; k < 8; k++) {
        const uint32_t kc = (uint32_t)(k * 16 + lcol) * 2;
        uint32_t af[2][4], bf[4][4];
        uint32_t A0 = sb + SM_A + (uint32_t)(wid * 32 + lrow) * LDAB + kc;
        ldm4(af[0][0], af[0][1], af[0][2], af[0][3], A0);
        ldm4(af[1][0], af[1][1], af[1][2], af[1][3], A0 + 16 * LDAB);
#pragma unroll
        for (int g = 0; g < 4; g++) {
            uint32_t B0 = sb + SM_B + (uint32_t)(g * 16 + lrow) * LDAB + kc;
            ldm4(bf[g][0], bf[g][1], bf[g][2], bf[g][3], B0);
        }
#pragma unroll
        for (int t = 0; t < 2; t++)
#pragma unroll
            for (int n = 0; n < 8; n++)
                mma16816(c[t][n], af[t][0], af[t][1], af[t][2], af[t][3],
                         bf[n >> 1][n & 1], bf[n >> 1][(n & 1) + 2]);
    }
    __syncthreads();
#pragma unroll
    for (int t = 0; t < 2; t++) {
        int r0 = wid * 32 + t * 16 + (lid >> 2);
#pragma unroll
        for (int n = 0; n < 8; n++) {
            int col = n * 8 + (lid & 3) * 2;
            *(float2*)(smem + SM_A + r0 * LDAB + col * 4) = make_float2(c[t][n][0], c[t][n][1]);
            *(float2*)(smem + SM_A + (r0 + 8) * LDAB + col * 4) = make_float2(c[t][n][2], c[t][n][3]);
        }
    }
    __syncthreads();
}

// ---------------- prep: W1 fp32 -> bf16 halves ----------------
__global__ void prep_kernel(const float* __restrict__ W1) {
    int i = blockIdx.x * blockDim.x + threadIdx.x;
    if (i < HDIM * MDIM) {
        int row = i >> 7, k = i & 127;
        g_W1m[i] = __float2bfloat16(W1[row * 256 + k]);
        g_W1t[i] = __float2bfloat16(W1[row * 256 + 128 + k]);
    }
}

// ---------------- zero d_out + sumw ----------------
__global__ void zero_kernel(float* __restrict__ agg) {
    int i = blockIdx.x * blockDim.x + threadIdx.x;
    int stride = gridDim.x * blockDim.x;
    float4 z = make_float4(0.f, 0.f, 0.f, 0.f);
    for (int j = i; j < NNODES * MDIM / 4; j += stride) ((float4*)agg)[j] = z;
    for (int j = i; j < NNODES; j += stride) g_sumw[j] = 0.f;
}

// ---------------- P = node_features @ W1t^T + b1 ----------------
__global__ void __launch_bounds__(128) pnode_kernel(const float* __restrict__ nf,
                                                    const float* __restrict__ b1) {
    extern __shared__ char smem[];
    const uint32_t sb = smem_u32(smem);
    const int tid = threadIdx.x, wid = tid >> 5, lid = tid & 31;
    const int base = blockIdx.x * 128;

    for (int i = tid; i < HDIM * DDIM / 2; i += 128) {
        int row = i >> 6, kp = i & 63;
        *(uint32_t*)(smem + SM_B + row * LDAB + kp * 4) = *(const uint32_t*)(g_W1t + row * DDIM + kp * 2);
    }
    const float4* nf4 = (const float4*)nf;
    for (int i = tid; i < 128 * 32; i += 128) {
        int row = i >> 5, c4 = i & 31;
        int node = base + row;
        float4 v = (node < NNODES) ? nf4[(size_t)node * 32 + c4] : make_float4(0.f, 0.f, 0.f, 0.f);
        __nv_bfloat162 lo = __floats2bfloat162_rn(v.x, v.y);
        __nv_bfloat162 hi = __floats2bfloat162_rn(v.z, v.w);
        uint2 u;
        u.x = *(uint32_t*)&lo;
        u.y = *(uint32_t*)&hi;
        *(uint2*)(smem + SM_A + row * LDAB + c4 * 8) = u;
    }
    if (tid < 64) ((float*)(smem + SM_VEC))[tid] = b1[tid];
    __syncthreads();

    gemm_128x64(smem, sb, wid, lid);

    int node = base + tid;
    if (node < NNODES) {
        const float* sb1 = (const float*)(smem + SM_VEC);
        const float* Crow = (const float*)(smem + SM_A + tid * LDAB);
        float4* Pr = (float4*)(g_P + (size_t)node * HDIM);
#pragma unroll
        for (int j = 0; j < 16; j++) {
            float4 cv = ((const float4*)Crow)[j];
            Pr[j] = make_float4(cv.x + sb1[4 * j], cv.y + sb1[4 * j + 1],
                                cv.z + sb1[4 * j + 2], cv.w + sb1[4 * j + 3]);
        }
    }
}

// ---------------- edge kernel: persistent producer/consumer pipeline ----------------
// 160 threads: warps 0-3 = consumers (GEMM+score+scatter), warp 4 = producer (staging).
__global__ void __launch_bounds__(160, 3) edge_kernel(const float* __restrict__ msg,
                                                      const int* __restrict__ tgt,
                                                      const float* __restrict__ W2,
                                                      float* __restrict__ agg) {
    extern __shared__ char smem[];
    const uint32_t sb = smem_u32(smem);
    const int tid = threadIdx.x, wid = tid >> 5, lid = tid & 31;

    // --- B = W1m bf16 [64][136] + W2, staged once by all 160 threads ---
    for (int i = tid; i < HDIM * 64; i += 160) {
        int row = i >> 6, kp = i & 63;
        *(uint32_t*)(smem + E_B + row * LDAB + kp * 4) = *(const uint32_t*)(g_W1m + row * MDIM + kp * 2);
    }
    if (tid < 64) ((float*)(smem + E_VEC))[tid] = W2[tid];
    __syncthreads();

    const float2* sW2 = (const float2*)(smem + E_VEC);

    if (wid == 4) {
        // ================= PRODUCER =================
        int nt = 0;
        for (int tile = blockIdx.x; tile < NTILES; tile += EGRID, nt++) {
            const int b = nt & 1;
            if (nt >= 2) bar_wait(3 + b, 160);            // wait buffer empty
            char* ap = smem + (b ? E_A1 : E_A0);          // GENERIC pointer for stores
            const float4* mt = (const float4*)msg + (size_t)tile * EM * 32;
            // stage A: 64 rows, one row per warp-iteration (coalesced 512B)
#pragma unroll 8
            for (int row = 0; row < EM; row++) {
                float4 v = mt[row * 32 + lid];
                __nv_bfloat162 lo = __floats2bfloat162_rn(v.x, v.y);
                __nv_bfloat162 hi = __floats2bfloat162_rn(v.z, v.w);
                uint2 u;
                u.x = *(uint32_t*)&lo;
                u.y = *(uint32_t*)&hi;
                *(uint2*)(ap + (uint32_t)row * LDAB + (uint32_t)lid * 8) = u;
            }
            // stage targets
            int* tgb = (int*)(smem + (b ? E_TG1 : E_TG0));
            tgb[lid] = tgt[tile * EM + lid];
            tgb[lid + 32] = tgt[tile * EM + lid + 32];
            asm volatile("membar.cta;" ::: "memory");     // STS visible before arrive
            bar_arrive(1 + b, 160);                       // buffer full
        }
    } else {
        // ================= CONSUMERS =================
        const int R = wid * 16;
        const int qr = lid >> 2, ql = lid & 3;
        const int lrow = lid & 15;
        const int lcolb = (lid >> 4) * 8;
        int nt = 0;
        for (int tile = blockIdx.x; tile < NTILES; tile += EGRID, nt++) {
            const int b = nt & 1;
            bar_wait(1 + b, 160);                         // wait buffer full
            const uint32_t abase = sb + (b ? E_A1 : E_A0);  // shared-space addr for ldmatrix
            const int* tgb = (const int*)(smem + (b ? E_TG1 : E_TG0));

            // P prefetch (hide L2 gather behind GEMM)
            const int te0 = tgb[R + qr];
            const int te1 = tgb[R + qr + 8];
            const float2* Pr0 = (const float2*)(g_P + (size_t)te0 * HDIM);
            const float2* Pr1 = (const float2*)(g_P + (size_t)te1 * HDIM);
            float2 pf0[8], pf1[8];
#pragma unroll
            for (int n = 0; n < 8; n++) {
                pf0[n] = Pr0[n * 4 + ql];
                pf1[n] = Pr1[n * 4 + ql];
            }

            // GEMM: m16n64k128, C in registers
            float c[8][4];
#pragma unroll
            for (int n = 0; n < 8; n++)
#pragma unroll
                for (int j = 0; j < 4; j++) c[n][j] = 0.f;
#pragma unroll
            for (int k = 0; k < 8; k++) {
                const uint32_t kc = (uint32_t)(k * 16 + lcolb) * 2;
                uint32_t af[4], bf[4][4];
                ldm4(af[0], af[1], af[2], af[3], abase + (uint32_t)(R + lrow) * LDAB + kc);
#pragma unroll
                for (int g = 0; g < 4; g++)
                    ldm4(bf[g][0], bf[g][1], bf[g][2], bf[g][3],
                         sb + E_B + (uint32_t)(g * 16 + lrow) * LDAB + kc);
#pragma unroll
                for (int n = 0; n < 8; n++)
                    mma16816(c[n], af[0], af[1], af[2], af[3],
                             bf[n >> 1][n & 1], bf[n >> 1][(n & 1) + 2]);
            }

            // epilogue: scores (all quad lanes end up with w0, w1)
            float r0 = 0.f, r1 = 0.f;
#pragma unroll
            for (int n = 0; n < 8; n++) {
                float2 w2 = sW2[n * 4 + ql];
                r0 = fmaf(gelu_fast(c[n][0] + pf0[n].x), w2.x, r0);
                r0 = fmaf(gelu_fast(c[n][1] + pf0[n].y), w2.y, r0);
                r1 = fmaf(gelu_fast(c[n][2] + pf1[n].x), w2.x, r1);
                r1 = fmaf(gelu_fast(c[n][3] + pf1[n].y), w2.y, r1);
            }
            r0 += __shfl_xor_sync(0xffffffffu, r0, 1);
            r0 += __shfl_xor_sync(0xffffffffu, r0, 2);
            r1 += __shfl_xor_sync(0xffffffffu, r1, 1);
            r1 += __shfl_xor_sync(0xffffffffu, r1, 2);
            float w0 = __fdividef(1.f, 1.f + __expf(-r0));
            float w1 = __fdividef(1.f, 1.f + __expf(-r1));
            if (ql == 0) {
                atomicAdd(&g_sumw[te0], w0);
                atomicAdd(&g_sumw[te1], w1);
            }

            // scatter: this warp's 16 rows; messages re-read from L2 (hot)
            const float4* mt = (const float4*)msg + (size_t)tile * EM * 32;
#pragma unroll
            for (int s = 0; s < 16; s++) {
                float w = __shfl_sync(0xffffffffu, s < 8 ? w0 : w1, 4 * (s & 7));
                int te = __shfl_sync(0xffffffffu, s < 8 ? te0 : te1, 4 * (s & 7));
                float4 v = mt[(R + s) * 32 + lid];
                red_add_v4(agg + (size_t)te * 128 + lid * 4,
                           make_float4(v.x * w, v.y * w, v.z * w, v.w * w));
            }
            bar_arrive(3 + b, 160);                       // buffer empty
        }
    }
}

// ---------------- finalize: divide by sumw + LayerNorm ----------------
__global__ void finalize_kernel(float* __restrict__ agg,
                                const float* __restrict__ gamma,
                                const float* __restrict__ beta) {
    int wid = threadIdx.x >> 5, lid = threadIdx.x & 31;
    int node = blockIdx.x * (blockDim.x >> 5) + wid;
    if (node >= NNODES) return;
    float inv = __fdividef(1.f, g_sumw[node] + 1e-8f);
    float4 v = ((const float4*)(agg + (size_t)node * 128))[lid];
    v.x *= inv; v.y *= inv; v.z *= inv; v.w *= inv;
    float s = v.x + v.y + v.z + v.w;
#pragma unroll
    for (int o = 16; o; o >>= 1) s += __shfl_xor_sync(0xffffffff, s, o);
    float mu = s * (1.f / 128.f);
    float dx = v.x - mu, dy = v.y - mu, dz = v.z - mu, dw = v.w - mu;
    float q = dx * dx + dy * dy + dz * dz + dw * dw;
#pragma unroll
    for (int o = 16; o; o >>= 1) q += __shfl_xor_sync(0xffffffff, q, o);
    float rs = rsqrtf(q * (1.f / 128.f) + 1e-5f);
    float4 g = ((const float4*)gamma)[lid];
    float4 b = ((const float4*)beta)[lid];
    ((float4*)(agg + (size_t)node * 128))[lid] =
        make_float4(dx * rs * g.x + b.x, dy * rs * g.y + b.y,
                    dz * rs * g.z + b.z, dw * rs * g.w + b.w);
}

// ---------------- launch ----------------
extern "C" void kernel_launch(void* const* d_in, const int* in_sizes, int n_in,
                              void* d_out, int out_size) {
    const float* msg = (const float*)d_in[0];
    const int* tgt = (const int*)d_in[1];
    const float* nf = (const float*)d_in[2];
    int wi = 3;
    for (int i = 3; i < n_in; i++) {
        if (in_sizes[i] == HDIM * (MDIM + DDIM)) { wi = i; break; }
    }
    const float* W1 = (const float*)d_in[wi];
    const float* b1 = (const float*)d_in[wi + 1];
    const float* W2 = (const float*)d_in[wi + 2];
    const float* gamma = (const float*)d_in[wi + 3];
    const float* beta = (const float*)d_in[wi + 4];
    float* agg = (float*)d_out;

    cudaFuncSetAttribute(pnode_kernel, cudaFuncAttributeMaxDynamicSharedMemorySize, SMEM_BYTES);
    cudaFuncSetAttribute(edge_kernel, cudaFuncAttributeMaxDynamicSharedMemorySize, E_SMEM);

    prep_kernel<<<32, 256>>>(W1);
    zero_kernel<<<512, 256>>>(agg);
    pnode_kernel<<<(NNODES + 127) / 128, 128, SMEM_BYTES>>>(nf, b1);
    edge_kernel<<<EGRID, 160, E_SMEM>>>(msg, tgt, W2, agg);
    finalize_kernel<<<(NNODES + 7) / 8, 256>>>(agg, gamma, beta);
}

// round 8
// speedup vs baseline: 1.0335x; 1.0335x over previous
#include <cuda_runtime.h>
#include <cuda_bf16.h>
#include <cstdint>

#define NNODES 50000
#define NEDGES 640000
#define MDIM 128
#define DDIM 128
#define HDIM 64

// ---------------- device scratch (static, no runtime alloc) ----------------
__device__ float g_P[(size_t)NNODES * HDIM];     // per-node projected features + b1
__device__ float g_sumw[NNODES];                 // sum of weights per node
__device__ __nv_bfloat16 g_W1m[HDIM * MDIM];     // W1[:, :128]  (message half), bf16
__device__ __nv_bfloat16 g_W1t[HDIM * DDIM];     // W1[:, 128:]  (node half),    bf16

#define LDA 136              // bf16 elements per row (8-elem pad -> conflict-free ldmatrix)
#define LDAB (LDA * 2)       // 272 bytes

// ------- pnode smem layout (C roundtrips through smem) -------
#define SM_VEC 0
#define SM_WT 256
#define SM_TG 768
#define SM_A 1280
#define SM_B (1280 + 34816)
#define SMEM_BYTES (SM_B + 17408)

// ------- edge smem layout (M=128 tile) -------
#define E_VEC 0                  // 64 floats: W2
#define E_WT 256                 // 128 floats: weights
#define E_TG 768                 // 128 ints: targets
#define E_A 1280                 // A bf16 [128][136] = 34816 B
#define E_B (1280 + 34816)       // B bf16 [64][136]  = 17408 B
#define E_SMEM (E_B + 17408)     // 53504 B -> 3 CTAs/SM (reg-capped)
#define EM 128                   // edges per CTA

// ---------------- helpers ----------------
__device__ __forceinline__ uint32_t smem_u32(const void* p) {
    uint32_t a;
    asm("{ .reg .u64 t; cvta.to.shared.u64 t, %1; cvt.u32.u64 %0, t; }" : "=r"(a) : "l"(p));
    return a;
}

__device__ __forceinline__ void ldm4(uint32_t& r0, uint32_t& r1, uint32_t& r2, uint32_t& r3,
                                     uint32_t addr) {
    asm volatile("ldmatrix.sync.aligned.m8n8.x4.shared.b16 {%0,%1,%2,%3}, [%4];"
                 : "=r"(r0), "=r"(r1), "=r"(r2), "=r"(r3) : "r"(addr));
}

__device__ __forceinline__ void mma16816(float* c, uint32_t a0, uint32_t a1, uint32_t a2,
                                         uint32_t a3, uint32_t b0, uint32_t b1) {
    asm volatile(
        "mma.sync.aligned.m16n8k16.row.col.f32.bf16.bf16.f32 "
        "{%0,%1,%2,%3}, {%4,%5,%6,%7}, {%8,%9}, {%0,%1,%2,%3};"
        : "+f"(c[0]), "+f"(c[1]), "+f"(c[2]), "+f"(c[3])
        : "r"(a0), "r"(a1), "r"(a2), "r"(a3), "r"(b0), "r"(b1));
}

__device__ __forceinline__ void red_add_v4(float* addr, float4 v) {
    asm volatile("red.global.add.v4.f32 [%0], {%1,%2,%3,%4};"
                 :: "l"(addr), "f"(v.x), "f"(v.y), "f"(v.z), "f"(v.w) : "memory");
}

// tanh-form gelu via MUFU (max dev from exact erf-gelu ~3e-4)
__device__ __forceinline__ float gelu_fast(float x) {
    float t = 1.5957692f * fmaf(0.044715f * x, x * x, x);
    return __fdividef(x, 1.0f + __expf(-t));
}

// ---------------- 128x64 GEMM (pnode only): C -> smem at SM_A ----------------
__device__ __forceinline__ void gemm_128x64(char* smem, uint32_t sb, int wid, int lid) {
    float c[2][8][4];
#pragma unroll
    for (int t = 0; t < 2; t++)
#pragma unroll
        for (int n = 0; n < 8; n++)
#pragma unroll
            for (int j = 0; j < 4; j++) c[t][n][j] = 0.f;

    const int lrow = lid & 15;
    const int lcol = (lid >> 4) * 8;

#pragma unroll
    for (int k = 0; k < 8; k++) {
        const uint32_t kc = (uint32_t)(k * 16 + lcol) * 2;
        uint32_t af[2][4], bf[4][4];
        uint32_t A0 = sb + SM_A + (uint32_t)(wid * 32 + lrow) * LDAB + kc;
        ldm4(af[0][0], af[0][1], af[0][2], af[0][3], A0);
        ldm4(af[1][0], af[1][1], af[1][2], af[1][3], A0 + 16 * LDAB);
#pragma unroll
        for (int g = 0; g < 4; g++) {
            uint32_t B0 = sb + SM_B + (uint32_t)(g * 16 + lrow) * LDAB + kc;
            ldm4(bf[g][0], bf[g][1], bf[g][2], bf[g][3], B0);
        }
#pragma unroll
        for (int t = 0; t < 2; t++)
#pragma unroll
            for (int n = 0; n < 8; n++)
                mma16816(c[t][n], af[t][0], af[t][1], af[t][2], af[t][3],
                         bf[n >> 1][n & 1], bf[n >> 1][(n & 1) + 2]);
    }
    __syncthreads();
#pragma unroll
    for (int t = 0; t < 2; t++) {
        int r0 = wid * 32 + t * 16 + (lid >> 2);
#pragma unroll
        for (int n = 0; n < 8; n++) {
            int col = n * 8 + (lid & 3) * 2;
            *(float2*)(smem + SM_A + r0 * LDAB + col * 4) = make_float2(c[t][n][0], c[t][n][1]);
            *(float2*)(smem + SM_A + (r0 + 8) * LDAB + col * 4) = make_float2(c[t][n][2], c[t][n][3]);
        }
    }
    __syncthreads();
}

// ---------------- prep: W1 fp32 -> bf16 halves ----------------
__global__ void prep_kernel(const float* __restrict__ W1) {
    int i = blockIdx.x * blockDim.x + threadIdx.x;
    if (i < HDIM * MDIM) {
        int row = i >> 7, k = i & 127;
        g_W1m[i] = __float2bfloat16(W1[row * 256 + k]);
        g_W1t[i] = __float2bfloat16(W1[row * 256 + 128 + k]);
    }
}

// ---------------- zero d_out + sumw ----------------
__global__ void zero_kernel(float* __restrict__ agg) {
    int i = blockIdx.x * blockDim.x + threadIdx.x;
    int stride = gridDim.x * blockDim.x;
    float4 z = make_float4(0.f, 0.f, 0.f, 0.f);
    for (int j = i; j < NNODES * MDIM / 4; j += stride) ((float4*)agg)[j] = z;
    for (int j = i; j < NNODES; j += stride) g_sumw[j] = 0.f;
}

// ---------------- P = node_features @ W1t^T + b1 ----------------
__global__ void __launch_bounds__(128) pnode_kernel(const float* __restrict__ nf,
                                                    const float* __restrict__ b1) {
    extern __shared__ char smem[];
    const uint32_t sb = smem_u32(smem);
    const int tid = threadIdx.x, wid = tid >> 5, lid = tid & 31;
    const int base = blockIdx.x * 128;

    for (int i = tid; i < HDIM * DDIM / 2; i += 128) {
        int row = i >> 6, kp = i & 63;
        *(uint32_t*)(smem + SM_B + row * LDAB + kp * 4) = *(const uint32_t*)(g_W1t + row * DDIM + kp * 2);
    }
    const float4* nf4 = (const float4*)nf;
    for (int i = tid; i < 128 * 32; i += 128) {
        int row = i >> 5, c4 = i & 31;
        int node = base + row;
        float4 v = (node < NNODES) ? nf4[(size_t)node * 32 + c4] : make_float4(0.f, 0.f, 0.f, 0.f);
        __nv_bfloat162 lo = __floats2bfloat162_rn(v.x, v.y);
        __nv_bfloat162 hi = __floats2bfloat162_rn(v.z, v.w);
        uint2 u;
        u.x = *(uint32_t*)&lo;
        u.y = *(uint32_t*)&hi;
        *(uint2*)(smem + SM_A + row * LDAB + c4 * 8) = u;
    }
    if (tid < 64) ((float*)(smem + SM_VEC))[tid] = b1[tid];
    __syncthreads();

    gemm_128x64(smem, sb, wid, lid);

    int node = base + tid;
    if (node < NNODES) {
        const float* sb1 = (const float*)(smem + SM_VEC);
        const float* Crow = (const float*)(smem + SM_A + tid * LDAB);
        float4* Pr = (float4*)(g_P + (size_t)node * HDIM);
#pragma unroll
        for (int j = 0; j < 16; j++) {
            float4 cv = ((const float4*)Crow)[j];
            Pr[j] = make_float4(cv.x + sb1[4 * j], cv.y + sb1[4 * j + 1],
                                cv.z + sb1[4 * j + 2], cv.w + sb1[4 * j + 3]);
        }
    }
}

// ---------------- main edge kernel: 4 warps x m32n64k128, pipelined P gather ------
__global__ void __launch_bounds__(128, 3) edge_kernel(const float* __restrict__ msg,
                                                      const int* __restrict__ tgt,
                                                      const float* __restrict__ W2,
                                                      float* __restrict__ agg) {
    extern __shared__ char smem[];
    const uint32_t sb = smem_u32(smem);
    const int tid = threadIdx.x, wid = tid >> 5, lid = tid & 31;
    const int base = blockIdx.x * EM;
    const int R = wid * 32;                 // this warp's 32 edge rows

    // --- stage B = W1m bf16 [64][136] ---
    for (int i = tid; i < HDIM * 64; i += 128) {
        int row = i >> 6, kp = i & 63;
        *(uint32_t*)(smem + E_B + row * LDAB + kp * 4) = *(const uint32_t*)(g_W1m + row * MDIM + kp * 2);
    }
    // --- stage A = messages fp32->bf16 [128][136] (one 512B row per warp-iter) ---
    const float4* m4 = (const float4*)msg + (size_t)base * 32;
#pragma unroll 8
    for (int i = 0; i < 32; i++) {
        const int row = wid + 4 * i;
        float4 v = m4[row * 32 + lid];
        __nv_bfloat162 lo = __floats2bfloat162_rn(v.x, v.y);
        __nv_bfloat162 hi = __floats2bfloat162_rn(v.z, v.w);
        uint2 u;
        u.x = *(uint32_t*)&lo;
        u.y = *(uint32_t*)&hi;
        *(uint2*)(smem + E_A + row * LDAB + lid * 8) = u;
    }
    if (tid < 64) ((float*)(smem + E_VEC))[tid] = W2[tid];
    if (tid < EM) ((int*)(smem + E_TG))[tid] = tgt[base + tid];
    __syncthreads();

    const int* st = (const int*)(smem + E_TG);
    const float2* sW2 = (const float2*)(smem + E_VEC);
    float* swt = (float*)(smem + E_WT);
    const int qr = lid >> 2, ql = lid & 3;
    const int lrow = lid & 15;
    const int lcolb = (lid >> 4) * 8;

    // --- P prefetch for m16-half 0 (rows R+qr, R+8+qr): hidden behind GEMM ---
    const int te00 = st[R + qr];
    const int te01 = st[R + 8 + qr];
    float2 pf0a[8], pf0b[8];
    {
        const float2* Pa = (const float2*)(g_P + (size_t)te00 * HDIM);
        const float2* Pb = (const float2*)(g_P + (size_t)te01 * HDIM);
#pragma unroll
        for (int n = 0; n < 8; n++) {
            pf0a[n] = Pa[n * 4 + ql];
            pf0b[n] = Pb[n * 4 + ql];
        }
    }

    // --- GEMM: m32n64k128 per warp, C in registers ---
    float c[2][8][4];
#pragma unroll
    for (int t = 0; t < 2; t++)
#pragma unroll
        for (int n = 0; n < 8; n++)
#pragma unroll
            for (int j = 0; j < 4; j++) c[t][n][j] = 0.f;

#pragma unroll
    for (int k = 0; k < 8; k++) {
        const uint32_t kc = (uint32_t)(k * 16 + lcolb) * 2;
        uint32_t af[2][4], bf[4][4];
        uint32_t A0 = sb + E_A + (uint32_t)(R + lrow) * LDAB + kc;
        ldm4(af[0][0], af[0][1], af[0][2], af[0][3], A0);
        ldm4(af[1][0], af[1][1], af[1][2], af[1][3], A0 + 16 * LDAB);
#pragma unroll
        for (int g = 0; g < 4; g++)
            ldm4(bf[g][0], bf[g][1], bf[g][2], bf[g][3],
                 sb + E_B + (uint32_t)(g * 16 + lrow) * LDAB + kc);
#pragma unroll
        for (int t = 0; t < 2; t++)
#pragma unroll
            for (int n = 0; n < 8; n++)
                mma16816(c[t][n], af[t][0], af[t][1], af[t][2], af[t][3],
                         bf[n >> 1][n & 1], bf[n >> 1][(n & 1) + 2]);
    }

    // --- P prefetch for m16-half 1 (rows R+16+qr, R+24+qr): hidden behind epi0 ---
    const int te10 = st[R + 16 + qr];
    const int te11 = st[R + 24 + qr];
    float2 pf1a[8], pf1b[8];
    {
        const float2* Pa = (const float2*)(g_P + (size_t)te10 * HDIM);
        const float2* Pb = (const float2*)(g_P + (size_t)te11 * HDIM);
#pragma unroll
        for (int n = 0; n < 8; n++) {
            pf1a[n] = Pa[n * 4 + ql];
            pf1b[n] = Pb[n * 4 + ql];
        }
    }

    // --- epilogue half 0 ---
    {
        float r0 = 0.f, r1 = 0.f;
#pragma unroll
        for (int n = 0; n < 8; n++) {
            float2 w2 = sW2[n * 4 + ql];
            r0 = fmaf(gelu_fast(c[0][n][0] + pf0a[n].x), w2.x, r0);
            r0 = fmaf(gelu_fast(c[0][n][1] + pf0a[n].y), w2.y, r0);
            r1 = fmaf(gelu_fast(c[0][n][2] + pf0b[n].x), w2.x, r1);
            r1 = fmaf(gelu_fast(c[0][n][3] + pf0b[n].y), w2.y, r1);
        }
        r0 += __shfl_xor_sync(0xffffffffu, r0, 1);
        r0 += __shfl_xor_sync(0xffffffffu, r0, 2);
        r1 += __shfl_xor_sync(0xffffffffu, r1, 1);
        r1 += __shfl_xor_sync(0xffffffffu, r1, 2);
        if (ql == 0) {
            float w0 = __fdividef(1.f, 1.f + __expf(-r0));
            float w1 = __fdividef(1.f, 1.f + __expf(-r1));
            swt[R + qr] = w0;
            swt[R + 8 + qr] = w1;
            atomicAdd(&g_sumw[te00], w0);
            atomicAdd(&g_sumw[te01], w1);
        }
    }
    // --- epilogue half 1 ---
    {
        float r0 = 0.f, r1 = 0.f;
#pragma unroll
        for (int n = 0; n < 8; n++) {
            float2 w2 = sW2[n * 4 + ql];
            r0 = fmaf(gelu_fast(c[1][n][0] + pf1a[n].x), w2.x, r0);
            r0 = fmaf(gelu_fast(c[1][n][1] + pf1a[n].y), w2.y, r0);
            r1 = fmaf(gelu_fast(c[1][n][2] + pf1b[n].x), w2.x, r1);
            r1 = fmaf(gelu_fast(c[1][n][3] + pf1b[n].y), w2.y, r1);
        }
        r0 += __shfl_xor_sync(0xffffffffu, r0, 1);
        r0 += __shfl_xor_sync(0xffffffffu, r0, 2);
        r1 += __shfl_xor_sync(0xffffffffu, r1, 1);
        r1 += __shfl_xor_sync(0xffffffffu, r1, 2);
        if (ql == 0) {
            float w0 = __fdividef(1.f, 1.f + __expf(-r0));
            float w1 = __fdividef(1.f, 1.f + __expf(-r1));
            swt[R + 16 + qr] = w0;
            swt[R + 24 + qr] = w1;
            atomicAdd(&g_sumw[te10], w0);
            atomicAdd(&g_sumw[te11], w1);
        }
    }
    __syncwarp();          // swt for this warp's rows written/read within the warp

    // --- weighted scatter: this warp's 32 rows (message re-read hits L1/L2) ---
#pragma unroll 8
    for (int i = 0; i < 32; i++) {
        const int row = R + i;
        float w = swt[row];
        int te = st[row];
        float4 v = m4[row * 32 + lid];
        red_add_v4(agg + (size_t)te * 128 + lid * 4,
                   make_float4(v.x * w, v.y * w, v.z * w, v.w * w));
    }
}

// ---------------- finalize: divide by sumw + LayerNorm ----------------
__global__ void finalize_kernel(float* __restrict__ agg,
                                const float* __restrict__ gamma,
                                const float* __restrict__ beta) {
    int wid = threadIdx.x >> 5, lid = threadIdx.x & 31;
    int node = blockIdx.x * (blockDim.x >> 5) + wid;
    if (node >= NNODES) return;
    float inv = __fdividef(1.f, g_sumw[node] + 1e-8f);
    float4 v = ((const float4*)(agg + (size_t)node * 128))[lid];
    v.x *= inv; v.y *= inv; v.z *= inv; v.w *= inv;
    float s = v.x + v.y + v.z + v.w;
#pragma unroll
    for (int o = 16; o; o >>= 1) s += __shfl_xor_sync(0xffffffff, s, o);
    float mu = s * (1.f / 128.f);
    float dx = v.x - mu, dy = v.y - mu, dz = v.z - mu, dw = v.w - mu;
    float q = dx * dx + dy * dy + dz * dz + dw * dw;
#pragma unroll
    for (int o = 16; o; o >>= 1) q += __shfl_xor_sync(0xffffffff, q, o);
    float rs = rsqrtf(q * (1.f / 128.f) + 1e-5f);
    float4 g = ((const float4*)gamma)[lid];
    float4 b = ((const float4*)beta)[lid];
    ((float4*)(agg + (size_t)node * 128))[lid] =
        make_float4(dx * rs * g.x + b.x, dy * rs * g.y + b.y,
                    dz * rs * g.z + b.z, dw * rs * g.w + b.w);
}

// ---------------- launch ----------------
extern "C" void kernel_launch(void* const* d_in, const int* in_sizes, int n_in,
                              void* d_out, int out_size) {
    const float* msg = (const float*)d_in[0];
    const int* tgt = (const int*)d_in[1];
    const float* nf = (const float*)d_in[2];
    int wi = 3;
    for (int i = 3; i < n_in; i++) {
        if (in_sizes[i] == HDIM * (MDIM + DDIM)) { wi = i; break; }
    }
    const float* W1 = (const float*)d_in[wi];
    const float* b1 = (const float*)d_in[wi + 1];
    const float* W2 = (const float*)d_in[wi + 2];
    const float* gamma = (const float*)d_in[wi + 3];
    const float* beta = (const float*)d_in[wi + 4];
    float* agg = (float*)d_out;

    cudaFuncSetAttribute(pnode_kernel, cudaFuncAttributeMaxDynamicSharedMemorySize, SMEM_BYTES);
    cudaFuncSetAttribute(edge_kernel, cudaFuncAttributeMaxDynamicSharedMemorySize, E_SMEM);

    prep_kernel<<<32, 256>>>(W1);
    zero_kernel<<<512, 256>>>(agg);
    pnode_kernel<<<(NNODES + 127) / 128, 128, SMEM_BYTES>>>(nf, b1);
    edge_kernel<<<NEDGES / EM, 128, E_SMEM>>>(msg, tgt, W2, agg);
    finalize_kernel<<<(NNODES + 7) / 8, 256>>>(agg, gamma, beta);
}

// round 9
// speedup vs baseline: 1.1253x; 1.0888x over previous
#include <cuda_runtime.h>
#include <cuda_bf16.h>
#include <cstdint>

#define NNODES 50000
#define NEDGES 640000
#define MDIM 128
#define DDIM 128
#define HDIM 64

// ---------------- device scratch (static, no runtime alloc) ----------------
__device__ __nv_bfloat16 g_P[(size_t)NNODES * HDIM]; // per-node projected feats + b1 (bf16)
__device__ float g_sumw[NNODES];                 // sum of weights per node
__device__ __nv_bfloat16 g_W1m[HDIM * MDIM];     // W1[:, :128]  (message half), bf16
__device__ __nv_bfloat16 g_W1t[HDIM * DDIM];     // W1[:, 128:]  (node half),    bf16

#define LDA 136              // bf16 elements per row (8-elem pad -> conflict-free ldmatrix)
#define LDAB (LDA * 2)       // 272 bytes

// ------- pnode smem layout (C roundtrips through smem) -------
#define SM_VEC 0
#define SM_WT 256
#define SM_TG 768
#define SM_A 1280
#define SM_B (1280 + 34816)
#define SMEM_BYTES (SM_B + 17408)

// ------- edge smem layout (M=64 tile) -------
#define E_VEC 0              // 64 floats: W2
#define E_WT 256             // 64 floats: weights
#define E_TG 512             // 64 ints: targets
#define E_A 1024             // A bf16 [64][136] = 17408 B
#define E_B (1024 + 17408)   // B bf16 [64][136] = 17408 B
#define E_SMEM (E_B + 17408) // 35840 B
#define EM 64                // edges per CTA

// ---------------- helpers ----------------
__device__ __forceinline__ uint32_t smem_u32(const void* p) {
    uint32_t a;
    asm("{ .reg .u64 t; cvta.to.shared.u64 t, %1; cvt.u32.u64 %0, t; }" : "=r"(a) : "l"(p));
    return a;
}

__device__ __forceinline__ void ldm4(uint32_t& r0, uint32_t& r1, uint32_t& r2, uint32_t& r3,
                                     uint32_t addr) {
    asm volatile("ldmatrix.sync.aligned.m8n8.x4.shared.b16 {%0,%1,%2,%3}, [%4];"
                 : "=r"(r0), "=r"(r1), "=r"(r2), "=r"(r3) : "r"(addr));
}

__device__ __forceinline__ void mma16816(float* c, uint32_t a0, uint32_t a1, uint32_t a2,
                                         uint32_t a3, uint32_t b0, uint32_t b1) {
    asm volatile(
        "mma.sync.aligned.m16n8k16.row.col.f32.bf16.bf16.f32 "
        "{%0,%1,%2,%3}, {%4,%5,%6,%7}, {%8,%9}, {%0,%1,%2,%3};"
        : "+f"(c[0]), "+f"(c[1]), "+f"(c[2]), "+f"(c[3])
        : "r"(a0), "r"(a1), "r"(a2), "r"(a3), "r"(b0), "r"(b1));
}

__device__ __forceinline__ void red_add_v4(float* addr, float4 v) {
    asm volatile("red.global.add.v4.f32 [%0], {%1,%2,%3,%4};"
                 :: "l"(addr), "f"(v.x), "f"(v.y), "f"(v.z), "f"(v.w) : "memory");
}

// tanh-form gelu via MUFU (max dev from exact erf-gelu ~3e-4)
__device__ __forceinline__ float gelu_fast(float x) {
    float t = 1.5957692f * fmaf(0.044715f * x, x * x, x);
    return __fdividef(x, 1.0f + __expf(-t));
}

// ---------------- 128x64 GEMM (pnode only): C -> smem at SM_A ----------------
__device__ __forceinline__ void gemm_128x64(char* smem, uint32_t sb, int wid, int lid) {
    float c[2][8][4];
#pragma unroll
    for (int t = 0; t < 2; t++)
#pragma unroll
        for (int n = 0; n < 8; n++)
#pragma unroll
            for (int j = 0; j < 4; j++) c[t][n][j] = 0.f;

    const int lrow = lid & 15;
    const int lcol = (lid >> 4) * 8;

#pragma unroll
    for (int k = 0; k < 8; k++) {
        const uint32_t kc = (uint32_t)(k * 16 + lcol) * 2;
        uint32_t af[2][4], bf[4][4];
        uint32_t A0 = sb + SM_A + (uint32_t)(wid * 32 + lrow) * LDAB + kc;
        ldm4(af[0][0], af[0][1], af[0][2], af[0][3], A0);
        ldm4(af[1][0], af[1][1], af[1][2], af[1][3], A0 + 16 * LDAB);
#pragma unroll
        for (int g = 0; g < 4; g++) {
            uint32_t B0 = sb + SM_B + (uint32_t)(g * 16 + lrow) * LDAB + kc;
            ldm4(bf[g][0], bf[g][1], bf[g][2], bf[g][3], B0);
        }
#pragma unroll
        for (int t = 0; t < 2; t++)
#pragma unroll
            for (int n = 0; n < 8; n++)
                mma16816(c[t][n], af[t][0], af[t][1], af[t][2], af[t][3],
                         bf[n >> 1][n & 1], bf[n >> 1][(n & 1) + 2]);
    }
    __syncthreads();
#pragma unroll
    for (int t = 0; t < 2; t++) {
        int r0 = wid * 32 + t * 16 + (lid >> 2);
#pragma unroll
        for (int n = 0; n < 8; n++) {
            int col = n * 8 + (lid & 3) * 2;
            *(float2*)(smem + SM_A + r0 * LDAB + col * 4) = make_float2(c[t][n][0], c[t][n][1]);
            *(float2*)(smem + SM_A + (r0 + 8) * LDAB + col * 4) = make_float2(c[t][n][2], c[t][n][3]);
        }
    }
    __syncthreads();
}

// ---------------- prep: W1 fp32 -> bf16 halves ----------------
__global__ void prep_kernel(const float* __restrict__ W1) {
    int i = blockIdx.x * blockDim.x + threadIdx.x;
    if (i < HDIM * MDIM) {
        int row = i >> 7, k = i & 127;
        g_W1m[i] = __float2bfloat16(W1[row * 256 + k]);
        g_W1t[i] = __float2bfloat16(W1[row * 256 + 128 + k]);
    }
}

// ---------------- zero d_out + sumw ----------------
__global__ void zero_kernel(float* __restrict__ agg) {
    int i = blockIdx.x * blockDim.x + threadIdx.x;
    int stride = gridDim.x * blockDim.x;
    float4 z = make_float4(0.f, 0.f, 0.f, 0.f);
    for (int j = i; j < NNODES * MDIM / 4; j += stride) ((float4*)agg)[j] = z;
    for (int j = i; j < NNODES; j += stride) g_sumw[j] = 0.f;
}

// ---------------- P = node_features @ W1t^T + b1 (stored bf16) ----------------
__global__ void __launch_bounds__(128) pnode_kernel(const float* __restrict__ nf,
                                                    const float* __restrict__ b1) {
    extern __shared__ char smem[];
    const uint32_t sb = smem_u32(smem);
    const int tid = threadIdx.x, wid = tid >> 5, lid = tid & 31;
    const int base = blockIdx.x * 128;

    for (int i = tid; i < HDIM * DDIM / 2; i += 128) {
        int row = i >> 6, kp = i & 63;
        *(uint32_t*)(smem + SM_B + row * LDAB + kp * 4) = *(const uint32_t*)(g_W1t + row * DDIM + kp * 2);
    }
    const float4* nf4 = (const float4*)nf;
    for (int i = tid; i < 128 * 32; i += 128) {
        int row = i >> 5, c4 = i & 31;
        int node = base + row;
        float4 v = (node < NNODES) ? nf4[(size_t)node * 32 + c4] : make_float4(0.f, 0.f, 0.f, 0.f);
        __nv_bfloat162 lo = __floats2bfloat162_rn(v.x, v.y);
        __nv_bfloat162 hi = __floats2bfloat162_rn(v.z, v.w);
        uint2 u;
        u.x = *(uint32_t*)&lo;
        u.y = *(uint32_t*)&hi;
        *(uint2*)(smem + SM_A + row * LDAB + c4 * 8) = u;
    }
    if (tid < 64) ((float*)(smem + SM_VEC))[tid] = b1[tid];
    __syncthreads();

    gemm_128x64(smem, sb, wid, lid);

    int node = base + tid;
    if (node < NNODES) {
        const float* sb1 = (const float*)(smem + SM_VEC);
        const float* Crow = (const float*)(smem + SM_A + tid * LDAB);
        uint32_t* Pr = (uint32_t*)(g_P + (size_t)node * HDIM);
#pragma unroll
        for (int j = 0; j < 16; j++) {
            float4 cv = ((const float4*)Crow)[j];
            __nv_bfloat162 p0 = __floats2bfloat162_rn(cv.x + sb1[4 * j], cv.y + sb1[4 * j + 1]);
            __nv_bfloat162 p1 = __floats2bfloat162_rn(cv.z + sb1[4 * j + 2], cv.w + sb1[4 * j + 3]);
            Pr[2 * j] = *(uint32_t*)&p0;
            Pr[2 * j + 1] = *(uint32_t*)&p1;
        }
    }
}

// ---------------- main edge kernel: reg-held messages + bf16 P prefetch ----------------
__global__ void __launch_bounds__(128, 4) edge_kernel(const float* __restrict__ msg,
                                                      const int* __restrict__ tgt,
                                                      const float* __restrict__ W2,
                                                      float* __restrict__ agg) {
    extern __shared__ char smem[];
    const uint32_t sb = smem_u32(smem);
    const int tid = threadIdx.x, wid = tid >> 5, lid = tid & 31;
    const int base = blockIdx.x * EM;
    const int R = wid * 16;                 // this warp's 16 epilogue rows

    // --- stage B = W1m bf16 [64][136] ---
    for (int i = tid; i < HDIM * 64; i += 128) {
        int row = i >> 6, kp = i & 63;
        *(uint32_t*)(smem + E_B + row * LDAB + kp * 4) = *(const uint32_t*)(g_W1m + row * MDIM + kp * 2);
    }
    // --- stage A = messages fp32->bf16 [64][136]; KEEP fp32 in registers ---
    const float4* m4 = (const float4*)msg + (size_t)base * 32;
    float4 mreg[16];                        // rows wid+4s, cols [4*lid, 4*lid+3]
#pragma unroll
    for (int s = 0; s < 16; s++) {
        const int row = wid + 4 * s;
        float4 v = m4[row * 32 + lid];
        mreg[s] = v;
        __nv_bfloat162 lo = __floats2bfloat162_rn(v.x, v.y);
        __nv_bfloat162 hi = __floats2bfloat162_rn(v.z, v.w);
        uint2 u;
        u.x = *(uint32_t*)&lo;
        u.y = *(uint32_t*)&hi;
        *(uint2*)(smem + E_A + row * LDAB + lid * 8) = u;
    }
    if (tid < 64) ((float*)(smem + E_VEC))[tid] = W2[tid];
    if (tid < EM) ((int*)(smem + E_TG))[tid] = tgt[base + tid];
    __syncthreads();

    // --- P prefetch (bf16x2 words; hide L2 gather latency behind GEMM) ---
    const int* st = (const int*)(smem + E_TG);
    const int qr = lid >> 2, ql = lid & 3;
    const int te0 = st[R + qr];
    const int te1 = st[R + qr + 8];
    const uint32_t* Pr0 = (const uint32_t*)(g_P + (size_t)te0 * HDIM);
    const uint32_t* Pr1 = (const uint32_t*)(g_P + (size_t)te1 * HDIM);
    uint32_t pf0[8], pf1[8];
#pragma unroll
    for (int n = 0; n < 8; n++) {
        pf0[n] = Pr0[n * 4 + ql];
        pf1[n] = Pr1[n * 4 + ql];
    }

    // --- GEMM: one m16n64k128 tile per warp, C in registers ---
    float c[8][4];
#pragma unroll
    for (int n = 0; n < 8; n++)
#pragma unroll
        for (int j = 0; j < 4; j++) c[n][j] = 0.f;

    const int lrow = lid & 15;
    const int lcolb = (lid >> 4) * 8;
#pragma unroll
    for (int k = 0; k < 8; k++) {
        const uint32_t kc = (uint32_t)(k * 16 + lcolb) * 2;
        uint32_t af[4], bf[4][4];
        ldm4(af[0], af[1], af[2], af[3], sb + E_A + (uint32_t)(R + lrow) * LDAB + kc);
#pragma unroll
        for (int g = 0; g < 4; g++)
            ldm4(bf[g][0], bf[g][1], bf[g][2], bf[g][3],
                 sb + E_B + (uint32_t)(g * 16 + lrow) * LDAB + kc);
#pragma unroll
        for (int n = 0; n < 8; n++)
            mma16816(c[n], af[0], af[1], af[2], af[3],
                     bf[n >> 1][n & 1], bf[n >> 1][(n & 1) + 2]);
    }

    // --- epilogue: score per row via quad reduction (uses prefetched bf16 P) ---
    const float2* sW2 = (const float2*)(smem + E_VEC);
    float* swt = (float*)(smem + E_WT);
    {
        float r0 = 0.f, r1 = 0.f;
#pragma unroll
        for (int n = 0; n < 8; n++) {
            float2 w2 = sW2[n * 4 + ql];
            float2 p0 = __bfloat1622float2(*(const __nv_bfloat162*)&pf0[n]);
            float2 p1 = __bfloat1622float2(*(const __nv_bfloat162*)&pf1[n]);
            r0 = fmaf(gelu_fast(c[n][0] + p0.x), w2.x, r0);
            r0 = fmaf(gelu_fast(c[n][1] + p0.y), w2.y, r0);
            r1 = fmaf(gelu_fast(c[n][2] + p1.x), w2.x, r1);
            r1 = fmaf(gelu_fast(c[n][3] + p1.y), w2.y, r1);
        }
        r0 += __shfl_xor_sync(0xffffffffu, r0, 1);
        r0 += __shfl_xor_sync(0xffffffffu, r0, 2);
        r1 += __shfl_xor_sync(0xffffffffu, r1, 1);
        r1 += __shfl_xor_sync(0xffffffffu, r1, 2);
        if (ql == 0) {
            float w0 = __fdividef(1.f, 1.f + __expf(-r0));
            float w1 = __fdividef(1.f, 1.f + __expf(-r1));
            swt[R + qr] = w0;
            swt[R + qr + 8] = w1;
            atomicAdd(&g_sumw[te0], w0);
            atomicAdd(&g_sumw[te1], w1);
        }
    }
    __syncthreads();       // weights visible to all warps

    // --- weighted scatter straight from registers (no re-read) ---
#pragma unroll
    for (int s = 0; s < 16; s++) {
        const int row = wid + 4 * s;
        float w = swt[row];
        int te = st[row];
        float4 v = mreg[s];
        red_add_v4(agg + (size_t)te * 128 + lid * 4,
                   make_float4(v.x * w, v.y * w, v.z * w, v.w * w));
    }
}

// ---------------- finalize: divide by sumw + LayerNorm ----------------
__global__ void finalize_kernel(float* __restrict__ agg,
                                const float* __restrict__ gamma,
                                const float* __restrict__ beta) {
    int wid = threadIdx.x >> 5, lid = threadIdx.x & 31;
    int node = blockIdx.x * (blockDim.x >> 5) + wid;
    if (node >= NNODES) return;
    float inv = __fdividef(1.f, g_sumw[node] + 1e-8f);
    float4 v = ((const float4*)(agg + (size_t)node * 128))[lid];
    v.x *= inv; v.y *= inv; v.z *= inv; v.w *= inv;
    float s = v.x + v.y + v.z + v.w;
#pragma unroll
    for (int o = 16; o; o >>= 1) s += __shfl_xor_sync(0xffffffff, s, o);
    float mu = s * (1.f / 128.f);
    float dx = v.x - mu, dy = v.y - mu, dz = v.z - mu, dw = v.w - mu;
    float q = dx * dx + dy * dy + dz * dz + dw * dw;
#pragma unroll
    for (int o = 16; o; o >>= 1) q += __shfl_xor_sync(0xffffffff, q, o);
    float rs = rsqrtf(q * (1.f / 128.f) + 1e-5f);
    float4 g = ((const float4*)gamma)[lid];
    float4 b = ((const float4*)beta)[lid];
    ((float4*)(agg + (size_t)node * 128))[lid] =
        make_float4(dx * rs * g.x + b.x, dy * rs * g.y + b.y,
                    dz * rs * g.z + b.z, dw * rs * g.w + b.w);
}

// ---------------- launch ----------------
extern "C" void kernel_launch(void* const* d_in, const int* in_sizes, int n_in,
                              void* d_out, int out_size) {
    const float* msg = (const float*)d_in[0];
    const int* tgt = (const int*)d_in[1];
    const float* nf = (const float*)d_in[2];
    int wi = 3;
    for (int i = 3; i < n_in; i++) {
        if (in_sizes[i] == HDIM * (MDIM + DDIM)) { wi = i; break; }
    }
    const float* W1 = (const float*)d_in[wi];
    const float* b1 = (const float*)d_in[wi + 1];
    const float* W2 = (const float*)d_in[wi + 2];
    const float* gamma = (const float*)d_in[wi + 3];
    const float* beta = (const float*)d_in[wi + 4];
    float* agg = (float*)d_out;

    cudaFuncSetAttribute(pnode_kernel, cudaFuncAttributeMaxDynamicSharedMemorySize, SMEM_BYTES);
    cudaFuncSetAttribute(edge_kernel, cudaFuncAttributeMaxDynamicSharedMemorySize, E_SMEM);

    prep_kernel<<<32, 256>>>(W1);
    zero_kernel<<<512, 256>>>(agg);
    pnode_kernel<<<(NNODES + 127) / 128, 128, SMEM_BYTES>>>(nf, b1);
    edge_kernel<<<NEDGES / EM, 128, E_SMEM>>>(msg, tgt, W2, agg);
    finalize_kernel<<<(NNODES + 7) / 8, 256>>>(agg, gamma, beta);
}